// round 7
// baseline (speedup 1.0000x reference)
#include <cuda_runtime.h>
#include <cuda_fp16.h>

#define N_NODES 50000
#define N_EDGES 1600000
#define IN_C    128
#define HEADS   4
#define OUT_C   16
#define HC      64   // HEADS*OUT_C

// ---------------- scratch (static device globals; no allocs allowed) --------
__device__ __align__(16) __half g_xwh[N_NODES * HC];    // projected, fp16
__device__ __align__(16) float  g_asrc[N_NODES * HEADS];
__device__ __align__(16) float  g_adst[N_NODES * HEADS];
__device__ __align__(16) float  g_denom[N_NODES * HEADS];
__device__ __align__(16) float  g_agg[N_NODES * HC];    // fp32 accumulators

// vectorized reduction (sm_90+): 16B atomic add, no return
__device__ __forceinline__ void red_add_v4(float* addr, float4 v) {
    asm volatile("red.global.add.v4.f32 [%0], {%1, %2, %3, %4};"
                 :: "l"(addr), "f"(v.x), "f"(v.y), "f"(v.z), "f"(v.w)
                 : "memory");
}

// ---------------- K0: zero accumulators -------------------------------------
__global__ void k_init(int n) {
    int t = blockIdx.x * blockDim.x + threadIdx.x;
    if (t < n * HC)    g_agg[t]   = 0.f;
    if (t < n * HEADS) g_denom[t] = 0.f;
}

// ---------------- K1: xw = x @ W -> fp16  ([N,128]@[128,64]) ----------------
__global__ void k_proj(const float* __restrict__ x, const float* __restrict__ W,
                       int n) {
    extern __shared__ float smem[];
    float* sW = smem;
    float* sx = smem + IN_C * HC;
    int tid = threadIdx.x;
    int row0 = blockIdx.x * 64;

    for (int i = tid; i < IN_C * HC / 4; i += 256)
        ((float4*)sW)[i] = ((const float4*)W)[i];
    for (int i = tid; i < 64 * IN_C / 4; i += 256) {
        int r = i >> 5;
        float4 v = make_float4(0.f, 0.f, 0.f, 0.f);
        if (row0 + r < n) v = ((const float4*)x)[(size_t)(row0 + r) * 32 + (i & 31)];
        ((float4*)sx)[i] = v;
    }
    __syncthreads();

    int rg = tid >> 4;
    int c4 = (tid & 15) * 4;
    unsigned long long a0[4], a1[4];
#pragma unroll
    for (int i = 0; i < 4; i++) { a0[i] = 0ull; a1[i] = 0ull; }

#pragma unroll 4
    for (int k = 0; k < IN_C; k++) {
        float4 w = *(const float4*)&sW[k * HC + c4];
        unsigned long long w01, w23;
        asm("mov.b64 %0, {%1, %2};" : "=l"(w01) : "f"(w.x), "f"(w.y));
        asm("mov.b64 %0, {%1, %2};" : "=l"(w23) : "f"(w.z), "f"(w.w));
#pragma unroll
        for (int i = 0; i < 4; i++) {
            float xv = sx[(rg * 4 + i) * IN_C + k];
            unsigned long long xp;
            asm("mov.b64 %0, {%1, %1};" : "=l"(xp) : "f"(xv));
            asm("fma.rn.f32x2 %0, %1, %2, %0;" : "+l"(a0[i]) : "l"(xp), "l"(w01));
            asm("fma.rn.f32x2 %0, %1, %2, %0;" : "+l"(a1[i]) : "l"(xp), "l"(w23));
        }
    }
#pragma unroll
    for (int i = 0; i < 4; i++) {
        int row = row0 + rg * 4 + i;
        if (row < n) {
            float4 o;
            asm("mov.b64 {%0, %1}, %2;" : "=f"(o.x), "=f"(o.y) : "l"(a0[i]));
            asm("mov.b64 {%0, %1}, %2;" : "=f"(o.z), "=f"(o.w) : "l"(a1[i]));
            __half2 p0 = __floats2half2_rn(o.x, o.y);
            __half2 p1 = __floats2half2_rn(o.z, o.w);
            uint2 u;
            u.x = *(unsigned*)&p0;
            u.y = *(unsigned*)&p1;
            *(uint2*)&g_xwh[row * HC + c4] = u;
        }
    }
}

// ---------------- K2: per-node attention logits (fp16 xw) -------------------
__global__ void k_att(const float* __restrict__ att_src,
                      const float* __restrict__ att_dst, int n) {
    int t = blockIdx.x * blockDim.x + threadIdx.x;
    if (t >= n * HEADS) return;
    int node = t >> 2, h = t & 3;
    const uint4* xp = (const uint4*)(g_xwh + node * HC + h * OUT_C);
    const float* as = att_src + h * OUT_C;
    const float* ad = att_dst + h * OUT_C;
    float ss = 0.f, sd = 0.f;
#pragma unroll
    for (int u = 0; u < 2; u++) {
        uint4 q = xp[u];
        unsigned w[4] = {q.x, q.y, q.z, q.w};
#pragma unroll
        for (int k = 0; k < 4; k++) {
            float2 f = __half22float2(*(__half2*)&w[k]);
            int c = u * 8 + k * 2;
            ss += f.x * as[c] + f.y * as[c + 1];
            sd += f.x * ad[c] + f.y * ad[c + 1];
        }
    }
    g_asrc[t] = ss;
    g_adst[t] = sd;
}

// ---------------- K3: fused edge pass, 17 REDG lanes/edge -------------------
// 16 threads/edge (warp = 2 edges). Thread q: head h=q>>2, channels [4q,4q+4).
// Message scatter: 16x red.v4. Denominator: the 4 head-exps (lanes 0,4,8,12 of
// each 16-lane group) are shuffled into lane 0, which issues ONE red.v4 —
// replacing 4 scalar red.f32 lanes (REDG-lane-throughput is the bottleneck).
__global__ void k_edge(const int* __restrict__ ei, int e) {
    int gid = blockIdx.x * blockDim.x + threadIdx.x;
    int eid = gid >> 4;
    int q = gid & 15;
    int h = q >> 2;
    bool valid = eid < e;
    int eidc = valid ? eid : e - 1;
    int s = __ldg(ei + eidc);
    int d = __ldg(ei + e + eidc);
    float a = g_asrc[s * 4 + h] + g_adst[d * 4 + h];
    a = a > 0.f ? a : 0.2f * a;
    float ex = __expf(a);

    // gather the 4 head-exps of this edge into lane (group base)
    unsigned base = threadIdx.x & 16u;               // 0 or 16 within warp
    float e1 = __shfl_sync(0xffffffffu, ex, base + 4);
    float e2 = __shfl_sync(0xffffffffu, ex, base + 8);
    float e3 = __shfl_sync(0xffffffffu, ex, base + 12);

    uint2 u = *(const uint2*)&g_xwh[s * HC + q * 4];
    float2 f0 = __half22float2(*(__half2*)&u.x);
    float2 f1 = __half22float2(*(__half2*)&u.y);
    float4 v = make_float4(f0.x * ex, f0.y * ex, f1.x * ex, f1.y * ex);
    if (valid) {
        red_add_v4(g_agg + d * HC + q * 4, v);
        if (q == 0)
            red_add_v4(g_denom + d * 4, make_float4(ex, e1, e2, e3));
    }
}

// ---------------- K4: normalize + ELU + output projection -------------------
__global__ void k_out(const float* __restrict__ bias,
                      const float* __restrict__ W_out,
                      const float* __restrict__ b_out,
                      float* __restrict__ y, int n) {
    int gid = blockIdx.x * blockDim.x + threadIdx.x;
    int node = gid >> 4;
    int q = gid & 15;
    bool valid = node < n;
    int nc = valid ? node : 0;

    float dn  = g_denom[nc * 4 + (q >> 2)];
    float inv = 1.f / (dn + 1e-16f);
    float4 a = *(const float4*)(g_agg + nc * HC + q * 4);
    float4 b = *(const float4*)(bias + q * 4);
    float4 w = *(const float4*)(W_out + q * 4);
    a.x = a.x * inv + b.x; a.y = a.y * inv + b.y;
    a.z = a.z * inv + b.z; a.w = a.w * inv + b.w;
    a.x = a.x > 0.f ? a.x : __expf(a.x) - 1.f;
    a.y = a.y > 0.f ? a.y : __expf(a.y) - 1.f;
    a.z = a.z > 0.f ? a.z : __expf(a.z) - 1.f;
    a.w = a.w > 0.f ? a.w : __expf(a.w) - 1.f;
    float p = a.x * w.x + a.y * w.y + a.z * w.z + a.w * w.w;
    p += __shfl_down_sync(0xffffffffu, p, 8, 16);
    p += __shfl_down_sync(0xffffffffu, p, 4, 16);
    p += __shfl_down_sync(0xffffffffu, p, 2, 16);
    p += __shfl_down_sync(0xffffffffu, p, 1, 16);
    if (valid && q == 0) y[node] = p + b_out[0];
}

// ---------------- launch -----------------------------------------------------
extern "C" void kernel_launch(void* const* d_in, const int* in_sizes, int n_in,
                              void* d_out, int out_size) {
    const float* x       = (const float*)d_in[0];
    const int*   ei      = (const int*)d_in[1];
    const float* W       = (const float*)d_in[2];
    const float* att_src = (const float*)d_in[3];
    const float* att_dst = (const float*)d_in[4];
    const float* bias    = (const float*)d_in[5];
    const float* W_out   = (const float*)d_in[6];
    const float* b_out   = (const float*)d_in[7];
    float*       y       = (float*)d_out;

    int n = in_sizes[0] / IN_C;   // 50000
    int e = in_sizes[1] / 2;      // 1600000

    const int B = 256;
    const int proj_smem = (IN_C * HC + 64 * IN_C) * (int)sizeof(float); // 64KB
    cudaFuncSetAttribute(k_proj, cudaFuncAttributeMaxDynamicSharedMemorySize,
                         proj_smem);

    k_init<<<(n * HC + B - 1) / B, B>>>(n);
    k_proj<<<(n + 63) / 64, 256, proj_smem>>>(x, W, n);
    k_att<<<(n * HEADS + B - 1) / B, B>>>(att_src, att_dst, n);
    k_edge<<<((size_t)e * 16 + B - 1) / B, B>>>(ei, e);
    k_out<<<(n * 16 + B - 1) / B, B>>>(bias, W_out, b_out, y, n);
}

// round 8
// speedup vs baseline: 1.5689x; 1.5689x over previous
#include <cuda_runtime.h>
#include <cuda_fp16.h>

#define N_NODES 50000
#define N_EDGES 1600000
#define IN_C    128
#define HEADS   4
#define OUT_C   16
#define HC      64   // HEADS*OUT_C

// ---------------- scratch (static device globals; no allocs allowed) --------
__device__ __align__(16) __half g_xwh[N_NODES * HC];    // projected, fp16
__device__ __align__(16) float  g_asrc[N_NODES * HEADS];
__device__ __align__(16) float  g_adst[N_NODES * HEADS];
__device__ __align__(16) float  g_denom[N_NODES * HEADS]; // fp32 (exact norm)
__device__ __align__(16) __half g_aggh[N_NODES * HC];   // fp16 accumulators

__device__ __forceinline__ void red_add_f32(float* addr, float v) {
    asm volatile("red.global.add.f32 [%0], %1;" :: "l"(addr), "f"(v) : "memory");
}
// 8-half vectorized reduction (sm_90+)
__device__ __forceinline__ void red_add_v4h2(__half* addr, unsigned r0,
                                             unsigned r1, unsigned r2,
                                             unsigned r3) {
    asm volatile("red.global.add.noftz.v4.f16x2 [%0], {%1, %2, %3, %4};"
                 :: "l"(addr), "r"(r0), "r"(r1), "r"(r2), "r"(r3)
                 : "memory");
}

// ---------------- K0: zero accumulators -------------------------------------
__global__ void k_init(int n) {
    int t = blockIdx.x * blockDim.x + threadIdx.x;
    if (t < n * HC / 8)    // 8 halves = 16B per thread
        *(uint4*)&g_aggh[t * 8] = make_uint4(0u, 0u, 0u, 0u);
    if (t < n * HEADS) g_denom[t] = 0.f;
}

// ---------------- K1: xw = x @ W -> fp16, fused attention logits ------------
// 256 threads, 64 rows/block. Thread = 4 rows x 4 cols, packed f32x2 FMA.
// Epilogue computes a_src/a_dst per (row, head) via 4-lane shuffle reduce.
__global__ void k_proj(const float* __restrict__ x, const float* __restrict__ W,
                       const float* __restrict__ att_src,
                       const float* __restrict__ att_dst, int n) {
    extern __shared__ float smem[];
    float* sW = smem;
    float* sx = smem + IN_C * HC;
    int tid = threadIdx.x;
    int row0 = blockIdx.x * 64;

    for (int i = tid; i < IN_C * HC / 4; i += 256)
        ((float4*)sW)[i] = ((const float4*)W)[i];
    for (int i = tid; i < 64 * IN_C / 4; i += 256) {
        int r = i >> 5;
        float4 v = make_float4(0.f, 0.f, 0.f, 0.f);
        if (row0 + r < n) v = ((const float4*)x)[(size_t)(row0 + r) * 32 + (i & 31)];
        ((float4*)sx)[i] = v;
    }
    __syncthreads();

    int rg = tid >> 4;
    int c4 = (tid & 15) * 4;     // global channel of this thread's 4 cols
    unsigned long long a0[4], a1[4];
#pragma unroll
    for (int i = 0; i < 4; i++) { a0[i] = 0ull; a1[i] = 0ull; }

#pragma unroll 4
    for (int k = 0; k < IN_C; k++) {
        float4 w = *(const float4*)&sW[k * HC + c4];
        unsigned long long w01, w23;
        asm("mov.b64 %0, {%1, %2};" : "=l"(w01) : "f"(w.x), "f"(w.y));
        asm("mov.b64 %0, {%1, %2};" : "=l"(w23) : "f"(w.z), "f"(w.w));
#pragma unroll
        for (int i = 0; i < 4; i++) {
            float xv = sx[(rg * 4 + i) * IN_C + k];
            unsigned long long xp;
            asm("mov.b64 %0, {%1, %1};" : "=l"(xp) : "f"(xv));
            asm("fma.rn.f32x2 %0, %1, %2, %0;" : "+l"(a0[i]) : "l"(xp), "l"(w01));
            asm("fma.rn.f32x2 %0, %1, %2, %0;" : "+l"(a1[i]) : "l"(xp), "l"(w23));
        }
    }

    // att vectors for this thread's 4 channels ([HEADS,OUT_C] is contiguous 64)
    float4 as = *(const float4*)(att_src + c4);
    float4 ad = *(const float4*)(att_dst + c4);
    int h = (tid & 15) >> 2;     // head of this 4-channel group

#pragma unroll
    for (int i = 0; i < 4; i++) {
        int row = row0 + rg * 4 + i;
        float4 o;
        asm("mov.b64 {%0, %1}, %2;" : "=f"(o.x), "=f"(o.y) : "l"(a0[i]));
        asm("mov.b64 {%0, %1}, %2;" : "=f"(o.z), "=f"(o.w) : "l"(a1[i]));
        if (row < n) {
            __half2 p0 = __floats2half2_rn(o.x, o.y);
            __half2 p1 = __floats2half2_rn(o.z, o.w);
            uint2 u;
            u.x = *(unsigned*)&p0;
            u.y = *(unsigned*)&p1;
            *(uint2*)&g_xwh[row * HC + c4] = u;
        }
        // fused logits: partial dot over 4 channels, reduce across 4 lanes
        float ss = o.x * as.x + o.y * as.y + o.z * as.z + o.w * as.w;
        float sd = o.x * ad.x + o.y * ad.y + o.z * ad.z + o.w * ad.w;
        ss += __shfl_down_sync(0xffffffffu, ss, 2);
        ss += __shfl_down_sync(0xffffffffu, ss, 1);
        sd += __shfl_down_sync(0xffffffffu, sd, 2);
        sd += __shfl_down_sync(0xffffffffu, sd, 1);
        if ((tid & 3) == 0 && row < n) {
            g_asrc[row * 4 + h] = ss;
            g_adst[row * 4 + h] = sd;
        }
    }
}

// ---------------- K2: fused edge pass, 8 lanes/edge, fp16x2 v4 reduction ----
// Thread q (0..7): head h=q>>1, channels [8q, 8q+8) as 4 x half2 (16B).
// No cross-lane dependencies (lesson from R7). Scatter = 1 cache line/edge.
__global__ void k_edge(const int* __restrict__ ei, int e) {
    int gid = blockIdx.x * blockDim.x + threadIdx.x;
    int eid = gid >> 3;
    if (eid >= e) return;
    int q = gid & 7;
    int h = q >> 1;
    int s = __ldg(ei + eid);
    int d = __ldg(ei + e + eid);
    float a = g_asrc[s * 4 + h] + g_adst[d * 4 + h];
    a = a > 0.f ? a : 0.2f * a;
    float ex = __expf(a);
    __half2 exh = __float2half2_rn(ex);
    uint4 u = *(const uint4*)&g_xwh[s * HC + q * 8];
    __half2 p0 = __hmul2(*(__half2*)&u.x, exh);
    __half2 p1 = __hmul2(*(__half2*)&u.y, exh);
    __half2 p2 = __hmul2(*(__half2*)&u.z, exh);
    __half2 p3 = __hmul2(*(__half2*)&u.w, exh);
    red_add_v4h2(g_aggh + d * HC + q * 8,
                 *(unsigned*)&p0, *(unsigned*)&p1,
                 *(unsigned*)&p2, *(unsigned*)&p3);
    if ((q & 1) == 0) red_add_f32(g_denom + d * 4 + h, ex);
}

// ---------------- K3: normalize + ELU + output projection -------------------
__global__ void k_out(const float* __restrict__ bias,
                      const float* __restrict__ W_out,
                      const float* __restrict__ b_out,
                      float* __restrict__ y, int n) {
    int gid = blockIdx.x * blockDim.x + threadIdx.x;
    int node = gid >> 4;
    int q = gid & 15;
    bool valid = node < n;
    int nc = valid ? node : 0;

    float dn  = g_denom[nc * 4 + (q >> 2)];
    float inv = 1.f / (dn + 1e-16f);
    uint2 u = *(const uint2*)&g_aggh[nc * HC + q * 4];
    float2 f0 = __half22float2(*(__half2*)&u.x);
    float2 f1 = __half22float2(*(__half2*)&u.y);
    float4 a = make_float4(f0.x, f0.y, f1.x, f1.y);
    float4 b = *(const float4*)(bias + q * 4);
    float4 w = *(const float4*)(W_out + q * 4);
    a.x = a.x * inv + b.x; a.y = a.y * inv + b.y;
    a.z = a.z * inv + b.z; a.w = a.w * inv + b.w;
    a.x = a.x > 0.f ? a.x : __expf(a.x) - 1.f;
    a.y = a.y > 0.f ? a.y : __expf(a.y) - 1.f;
    a.z = a.z > 0.f ? a.z : __expf(a.z) - 1.f;
    a.w = a.w > 0.f ? a.w : __expf(a.w) - 1.f;
    float p = a.x * w.x + a.y * w.y + a.z * w.z + a.w * w.w;
    p += __shfl_down_sync(0xffffffffu, p, 8, 16);
    p += __shfl_down_sync(0xffffffffu, p, 4, 16);
    p += __shfl_down_sync(0xffffffffu, p, 2, 16);
    p += __shfl_down_sync(0xffffffffu, p, 1, 16);
    if (valid && q == 0) y[node] = p + b_out[0];
}

// ---------------- launch -----------------------------------------------------
extern "C" void kernel_launch(void* const* d_in, const int* in_sizes, int n_in,
                              void* d_out, int out_size) {
    const float* x       = (const float*)d_in[0];
    const int*   ei      = (const int*)d_in[1];
    const float* W       = (const float*)d_in[2];
    const float* att_src = (const float*)d_in[3];
    const float* att_dst = (const float*)d_in[4];
    const float* bias    = (const float*)d_in[5];
    const float* W_out   = (const float*)d_in[6];
    const float* b_out   = (const float*)d_in[7];
    float*       y       = (float*)d_out;

    int n = in_sizes[0] / IN_C;   // 50000
    int e = in_sizes[1] / 2;      // 1600000

    const int B = 256;
    const int proj_smem = (IN_C * HC + 64 * IN_C) * (int)sizeof(float); // 64KB
    cudaFuncSetAttribute(k_proj, cudaFuncAttributeMaxDynamicSharedMemorySize,
                         proj_smem);

    k_init<<<(n * HC / 8 + B - 1) / B, B>>>(n);
    k_proj<<<(n + 63) / 64, 256, proj_smem>>>(x, W, att_src, att_dst, n);
    k_edge<<<((size_t)e * 8 + B - 1) / B, B>>>(ei, e);
    k_out<<<(n * 16 + B - 1) / B, B>>>(bias, W_out, b_out, y, n);
}